// round 2
// baseline (speedup 1.0000x reference)
#include <cuda_runtime.h>

#define NPTS 8192
#define DIM  128
#define MARGIN 1.0f
#define EPSV 1e-16f

#define TILE 128
#define KC   32      // K chunk
#define PAD  132     // smem row stride (floats)

// Scratch (no allocations allowed)
__device__ float g_S[NPTS];
__device__ float g_sq[NPTS];
__device__ int   g_lab[NPTS];
__device__ int   g_step;     // 1 = labels int32, 2 = labels int64
__device__ double g_loss;
__device__ unsigned long long g_cnt;

// ------------------------------------------------------------ label dtype detect
// int64 little-endian labels in [0,64): all odd 32-bit words are 0.
// int32 labels: odd words are random labels; P(all zero) ~ (1/64)^4096 ~ 0.
__global__ void k_detect(const int* __restrict__ lab32) {
    __shared__ int red[256];
    int t = threadIdx.x;
    int acc = 0;
    for (int i = 2 * t + 1; i < NPTS; i += 2 * 256) acc |= lab32[i];
    red[t] = acc;
    __syncthreads();
    for (int off = 128; off; off >>= 1) {
        if (t < off) red[t] |= red[t + off];
        __syncthreads();
    }
    if (t == 0) g_step = (red[0] == 0) ? 2 : 1;
}

__global__ void k_conv(const int* __restrict__ lab32) {
    int i = blockIdx.x * blockDim.x + threadIdx.x;
    int step = g_step;
    if (i < NPTS) g_lab[i] = lab32[i * step];
}

// ---------------------------------------------------------------- init + sq
__global__ void k_init() {
    int i = blockIdx.x * blockDim.x + threadIdx.x;
    if (i < NPTS) g_S[i] = 0.0f;
    if (i == 0) { g_loss = 0.0; g_cnt = 0ull; }
}

__global__ void k_sq(const float* __restrict__ f) {
    int warp = (blockIdx.x * blockDim.x + threadIdx.x) >> 5;
    int lane = threadIdx.x & 31;
    if (warp >= NPTS) return;
    const float* row = f + (size_t)warp * DIM;
    float s = 0.0f;
    #pragma unroll
    for (int k = lane; k < DIM; k += 32) { float v = row[k]; s = fmaf(v, v, s); }
    #pragma unroll
    for (int off = 16; off; off >>= 1) s += __shfl_down_sync(0xffffffffu, s, off);
    if (lane == 0) g_sq[warp] = s;
}

// ------------------------------------------------- main: Gram + S epilogue
__global__ __launch_bounds__(256) void k_S(const float* __restrict__ f) {
    __shared__ float As[KC * PAD];  // K-major: As[k][m]
    __shared__ float Bs[KC * PAD];  // K-major: Bs[k][n]

    const int it = blockIdx.y, jt = blockIdx.x;
    const int t  = threadIdx.x;
    const int tx = t & 15, ty = t >> 4;

    const float* Ag = f + (size_t)it * TILE * DIM;
    const float* Bg = f + (size_t)jt * TILE * DIM;

    float acc[8][8];
    #pragma unroll
    for (int a = 0; a < 8; a++)
        #pragma unroll
        for (int b = 0; b < 8; b++) acc[a][b] = 0.0f;

    for (int kc = 0; kc < DIM / KC; kc++) {
        #pragma unroll
        for (int iter = 0; iter < 4; iter++) {
            int idx = iter * 256 + t;
            int row = idx >> 3;
            int c4l = idx & 7;
            float4 a = reinterpret_cast<const float4*>(Ag)[row * (DIM / 4) + kc * (KC / 4) + c4l];
            float4 b = reinterpret_cast<const float4*>(Bg)[row * (DIM / 4) + kc * (KC / 4) + c4l];
            int c = c4l * 4;
            As[(c + 0) * PAD + row] = a.x; As[(c + 1) * PAD + row] = a.y;
            As[(c + 2) * PAD + row] = a.z; As[(c + 3) * PAD + row] = a.w;
            Bs[(c + 0) * PAD + row] = b.x; Bs[(c + 1) * PAD + row] = b.y;
            Bs[(c + 2) * PAD + row] = b.z; Bs[(c + 3) * PAD + row] = b.w;
        }
        __syncthreads();

        #pragma unroll
        for (int k = 0; k < KC; k++) {
            float4 a0 = *reinterpret_cast<const float4*>(&As[k * PAD + ty * 8]);
            float4 a1 = *reinterpret_cast<const float4*>(&As[k * PAD + ty * 8 + 4]);
            float4 b0 = *reinterpret_cast<const float4*>(&Bs[k * PAD + tx * 8]);
            float4 b1 = *reinterpret_cast<const float4*>(&Bs[k * PAD + tx * 8 + 4]);
            float av[8] = {a0.x, a0.y, a0.z, a0.w, a1.x, a1.y, a1.z, a1.w};
            float bv[8] = {b0.x, b0.y, b0.z, b0.w, b1.x, b1.y, b1.z, b1.w};
            #pragma unroll
            for (int mi = 0; mi < 8; mi++)
                #pragma unroll
                for (int ni = 0; ni < 8; ni++)
                    acc[mi][ni] = fmaf(av[mi], bv[ni], acc[mi][ni]);
        }
        __syncthreads();
    }

    const int i0 = it * TILE + ty * 8;
    const int j0 = jt * TILE + tx * 8;
    float sqi[8], sqj[8];
    int li[8], lj[8];
    #pragma unroll
    for (int mi = 0; mi < 8; mi++) { sqi[mi] = g_sq[i0 + mi]; li[mi] = g_lab[i0 + mi]; }
    #pragma unroll
    for (int ni = 0; ni < 8; ni++) { sqj[ni] = g_sq[j0 + ni]; lj[ni] = g_lab[j0 + ni]; }

    float srow[8];
    #pragma unroll
    for (int mi = 0; mi < 8; mi++) srow[mi] = 0.0f;

    #pragma unroll
    for (int mi = 0; mi < 8; mi++) {
        #pragma unroll
        for (int ni = 0; ni < 8; ni++) {
            float d2 = sqi[mi] + sqj[ni] - 2.0f * acc[mi][ni];
            float d  = sqrtf(fmaxf(d2, EPSV));
            if (li[mi] != lj[ni]) srow[mi] += expf(MARGIN - d);
        }
    }

    #pragma unroll
    for (int mi = 0; mi < 8; mi++) {
        float v = srow[mi];
        #pragma unroll
        for (int off = 8; off; off >>= 1) v += __shfl_down_sync(0xffffffffu, v, off, 16);
        if (tx == 0) atomicAdd(&g_S[i0 + mi], v);
    }
}

// ---------------------------------------------- positive-pair loss accumulate
__global__ __launch_bounds__(128) void k_loss(const float* __restrict__ f) {
    const int i = blockIdx.x;
    const int t = threadIdx.x;
    __shared__ float fi[DIM];
    __shared__ float redf[128];
    __shared__ int   redi[128];

    fi[t] = f[(size_t)i * DIM + t];
    __syncthreads();

    const int   li  = g_lab[i];
    const float Si  = g_S[i];
    const float sqi = g_sq[i];

    float part = 0.0f;
    int   cnt  = 0;
    for (int j = t; j < NPTS; j += 128) {
        if (g_lab[j] == li) {
            const float4* fj = reinterpret_cast<const float4*>(f + (size_t)j * DIM);
            float dot = 0.0f;
            #pragma unroll
            for (int k4 = 0; k4 < DIM / 4; k4++) {
                float4 b = fj[k4];
                dot = fmaf(fi[k4 * 4 + 0], b.x, dot);
                dot = fmaf(fi[k4 * 4 + 1], b.y, dot);
                dot = fmaf(fi[k4 * 4 + 2], b.z, dot);
                dot = fmaf(fi[k4 * 4 + 3], b.w, dot);
            }
            float d2 = sqi + g_sq[j] - 2.0f * dot;
            float d  = sqrtf(fmaxf(d2, EPSV));
            float J  = logf(Si + g_S[j]) + d;
            float h  = fmaxf(J, 0.0f);
            part = fmaf(h, h, part);
            cnt++;
        }
    }

    redf[t] = part; redi[t] = cnt;
    __syncthreads();
    #pragma unroll
    for (int off = 64; off; off >>= 1) {
        if (t < off) { redf[t] += redf[t + off]; redi[t] += redi[t + off]; }
        __syncthreads();
    }
    if (t == 0) {
        atomicAdd(&g_loss, (double)redf[0]);
        atomicAdd(&g_cnt, (unsigned long long)redi[0]);
    }
}

__global__ void k_final(float* out) {
    out[0] = (float)(g_loss / (2.0 * (double)g_cnt));
}

extern "C" void kernel_launch(void* const* d_in, const int* in_sizes, int n_in,
                              void* d_out, int out_size) {
    const float* f     = (const float*)d_in[0];
    const int*   lab32 = (const int*)d_in[1];
    float*       out   = (float*)d_out;

    k_detect<<<1, 256>>>(lab32);
    k_conv<<<(NPTS + 255) / 256, 256>>>(lab32);
    k_init<<<(NPTS + 255) / 256, 256>>>();
    k_sq<<<NPTS / 8, 256>>>(f);

    dim3 grid(NPTS / TILE, NPTS / TILE);
    k_S<<<grid, 256>>>(f);

    k_loss<<<NPTS, 128>>>(f);
    k_final<<<1, 1>>>(out);
}

// round 5
// speedup vs baseline: 5.3005x; 5.3005x over previous
#include <cuda_runtime.h>
#include <cuda_bf16.h>

#define NPTS 8192
#define DIM  128
#define TILE 128
#define NT   (NPTS/TILE)          // 64
#define NTILES (NT*(NT+1)/2)      // 2080
#define MARGIN 1.0f
#define EPSV 1e-16f
#define PAIR_CAP 2500000
#define STRIDE 136                // smem row stride (bf16 elems): conflict-free ldmatrix

// ---------------- device scratch ----------------
__device__ float g_S[NPTS];
__device__ float g_sq[NPTS];
__device__ int   g_lab[NPTS];
__device__ int   g_step;
__device__ double g_loss;
__device__ unsigned long long g_cnt;
__device__ unsigned g_np;
__device__ uint4 g_hi[NPTS*DIM/8];
__device__ uint4 g_lo[NPTS*DIM/8];
__device__ uint2 g_pairs[PAIR_CAP];

// ---------------- smem layout (bytes) ----------------
#define SM_AH  0
#define SM_AL  (128*STRIDE*2)
#define SM_BH  (2*128*STRIDE*2)
#define SM_BL  (3*128*STRIDE*2)
#define SM_SQI (4*128*STRIDE*2)        // 139264
#define SM_SQJ (SM_SQI + 512)
#define SM_LI  (SM_SQJ + 512)
#define SM_LJ  (SM_LI  + 512)
#define SM_ROWS (SM_LJ + 512)
#define SM_COLS (SM_ROWS + 512)
#define SM_CNT (SM_COLS + 512)
#define SM_GB  (SM_CNT + 4)
#define SM_TOTAL (SM_GB + 12)
#define SM_PBUF SM_AH                  // pair buffer overlays A_hi after MMA phase
#define PBUF_CAP 4096

__device__ __forceinline__ unsigned smem_u32(const void* p) {
    unsigned a;
    asm("{ .reg .u64 t; cvta.to.shared.u64 t, %1; cvt.u32.u64 %0, t; }" : "=r"(a) : "l"(p));
    return a;
}

#define LDSM4(R, a) asm volatile( \
    "ldmatrix.sync.aligned.m8n8.x4.shared.b16 {%0,%1,%2,%3}, [%4];" \
    : "=r"((R)[0]), "=r"((R)[1]), "=r"((R)[2]), "=r"((R)[3]) : "r"(a))

#define MMA(d, a, b) asm volatile( \
    "mma.sync.aligned.m16n8k16.row.col.f32.bf16.bf16.f32 " \
    "{%0,%1,%2,%3}, {%4,%5,%6,%7}, {%8,%9}, {%0,%1,%2,%3};" \
    : "+f"((d)[0]), "+f"((d)[1]), "+f"((d)[2]), "+f"((d)[3]) \
    : "r"((a)[0]), "r"((a)[1]), "r"((a)[2]), "r"((a)[3]), "r"((b)[0]), "r"((b)[1]))

// ---------------- label dtype detect + convert ----------------
__global__ void k_detect(const int* __restrict__ lab32) {
    __shared__ int red[256];
    int t = threadIdx.x, acc = 0;
    for (int i = 2 * t + 1; i < NPTS; i += 512) acc |= lab32[i];
    red[t] = acc; __syncthreads();
    for (int off = 128; off; off >>= 1) { if (t < off) red[t] |= red[t + off]; __syncthreads(); }
    if (t == 0) g_step = (red[0] == 0) ? 2 : 1;
}
__global__ void k_conv(const int* __restrict__ lab32) {
    int i = blockIdx.x * blockDim.x + threadIdx.x;
    if (i < NPTS) g_lab[i] = lab32[i * g_step];
}

// ---------------- init / sq / bf16 split ----------------
__global__ void k_init() {
    int i = blockIdx.x * blockDim.x + threadIdx.x;
    if (i < NPTS) g_S[i] = 0.0f;
    if (i == 0) { g_loss = 0.0; g_cnt = 0ull; g_np = 0u; }
}
__global__ void k_sq(const float* __restrict__ f) {
    int warp = (blockIdx.x * blockDim.x + threadIdx.x) >> 5;
    int lane = threadIdx.x & 31;
    if (warp >= NPTS) return;
    const float* row = f + (size_t)warp * DIM;
    float s = 0.0f;
    #pragma unroll
    for (int k = lane; k < DIM; k += 32) { float v = row[k]; s = fmaf(v, v, s); }
    #pragma unroll
    for (int off = 16; off; off >>= 1) s += __shfl_down_sync(0xffffffffu, s, off);
    if (lane == 0) g_sq[warp] = s;
}
__global__ void k_split(const float* __restrict__ f) {
    int idx = blockIdx.x * blockDim.x + threadIdx.x;
    if (idx >= NPTS * DIM / 8) return;
    const float4* f4 = (const float4*)f;
    float4 a = f4[idx * 2], b = f4[idx * 2 + 1];
    float v[8] = {a.x, a.y, a.z, a.w, b.x, b.y, b.z, b.w};
    unsigned hw[4], lw[4];
    #pragma unroll
    for (int p = 0; p < 4; p++) {
        float x0 = v[2 * p], x1 = v[2 * p + 1];
        __nv_bfloat16 bh0 = __float2bfloat16(x0);
        __nv_bfloat16 bh1 = __float2bfloat16(x1);
        __nv_bfloat16 bl0 = __float2bfloat16(x0 - __bfloat162float(bh0));
        __nv_bfloat16 bl1 = __float2bfloat16(x1 - __bfloat162float(bh1));
        hw[p] = (unsigned)__bfloat16_as_ushort(bh0) | ((unsigned)__bfloat16_as_ushort(bh1) << 16);
        lw[p] = (unsigned)__bfloat16_as_ushort(bl0) | ((unsigned)__bfloat16_as_ushort(bl1) << 16);
    }
    g_hi[idx] = make_uint4(hw[0], hw[1], hw[2], hw[3]);
    g_lo[idx] = make_uint4(lw[0], lw[1], lw[2], lw[3]);
}

// ---------------- main: HMMA Gram tile + fused epilogue ----------------
__global__ void __launch_bounds__(256, 1) k_S() {
    extern __shared__ char smem[];
    const unsigned sb = smem_u32(smem);
    float* s_sqi  = (float*)(smem + SM_SQI);
    float* s_sqj  = (float*)(smem + SM_SQJ);
    int*   s_li   = (int*)  (smem + SM_LI);
    int*   s_lj   = (int*)  (smem + SM_LJ);
    float* s_rowS = (float*)(smem + SM_ROWS);
    float* s_colS = (float*)(smem + SM_COLS);
    unsigned* s_cnt = (unsigned*)(smem + SM_CNT);
    unsigned* s_gb  = (unsigned*)(smem + SM_GB);

    const int t = threadIdx.x, w = t >> 5, lane = t & 31;

    // upper-triangle tile map
    int b = blockIdx.x, it = 0, base = 0;
    while (b >= base + (NT - it)) { base += NT - it; it++; }
    const int jt = it + (b - base);
    const bool offdiag = (it != jt);

    // ---- stage tiles into smem (row-major, STRIDE elems/row) ----
    {
        const uint4* srcs[4] = {
            g_hi + (size_t)it * TILE * (DIM / 8), g_lo + (size_t)it * TILE * (DIM / 8),
            g_hi + (size_t)jt * TILE * (DIM / 8), g_lo + (size_t)jt * TILE * (DIM / 8) };
        const unsigned dsts[4] = { SM_AH, SM_AL, SM_BH, SM_BL };
        #pragma unroll
        for (int m = 0; m < 4; m++)
            for (int i2 = t; i2 < 128 * 16; i2 += 256) {
                int r = i2 >> 4, q = i2 & 15;           // row, uint4-within-row
                uint4 v = srcs[m][(size_t)r * 16 + q];
                *(uint4*)(smem + dsts[m] + (r * STRIDE + q * 8) * 2) = v;
            }
    }
    if (t < 128) { s_sqi[t] = g_sq[it * TILE + t]; s_li[t] = g_lab[it * TILE + t];
                   s_rowS[t] = 0.0f; s_colS[t] = 0.0f; }
    else { int u = t - 128; s_sqj[u] = g_sq[jt * TILE + u]; s_lj[u] = g_lab[jt * TILE + u]; }
    if (t == 0) *s_cnt = 0u;
    __syncthreads();

    // ---- warp subtile: 32 rows x 64 cols ----
    const int mb = (w & 3) * 32;          // m-block within tile
    const int nb = (w >> 2) * 64;         // n-block within tile

    float acc[2][8][4];
    #pragma unroll
    for (int mt = 0; mt < 2; mt++)
        #pragma unroll
        for (int nt = 0; nt < 8; nt++)
            #pragma unroll
            for (int e = 0; e < 4; e++) acc[mt][nt][e] = 0.0f;

    // precomputed lane addressing
    const unsigned a_row = mb + (lane & 15);
    const unsigned a_col0 = (lane >> 4) * 8;
    const unsigned b_row = nb + (lane & 7) + ((lane >> 4) << 3);
    const unsigned b_col0 = ((lane >> 3) & 1) * 8;

    #pragma unroll
    for (int ks = 0; ks < 8; ks++) {
        const unsigned kc = ks * 16;
        unsigned ah[2][4], al[2][4], bh[8][2], bl[8][2];
        #pragma unroll
        for (int mt = 0; mt < 2; mt++) {
            unsigned off = ((a_row + mt * 16) * STRIDE + kc + a_col0) * 2;
            LDSM4(ah[mt], sb + SM_AH + off);
            LDSM4(al[mt], sb + SM_AL + off);
        }
        #pragma unroll
        for (int np = 0; np < 4; np++) {
            unsigned off = ((b_row + np * 16) * STRIDE + kc + b_col0) * 2;
            unsigned th[4], tl[4];
            LDSM4(th, sb + SM_BH + off);
            LDSM4(tl, sb + SM_BL + off);
            bh[2*np][0] = th[0]; bh[2*np][1] = th[1]; bh[2*np+1][0] = th[2]; bh[2*np+1][1] = th[3];
            bl[2*np][0] = tl[0]; bl[2*np][1] = tl[1]; bl[2*np+1][0] = tl[2]; bl[2*np+1][1] = tl[3];
        }
        #pragma unroll
        for (int mt = 0; mt < 2; mt++)
            #pragma unroll
            for (int nt = 0; nt < 8; nt++) {
                MMA(acc[mt][nt], ah[mt], bh[nt]);
                MMA(acc[mt][nt], ah[mt], bl[nt]);
                MMA(acc[mt][nt], al[mt], bh[nt]);
            }
    }
    __syncthreads();   // smem tiles no longer needed; pair buffer may overlay

    // ---- epilogue ----
    const int r = lane >> 2, cb = (lane & 3) * 2;
    float sqi_r[4]; int li_r[4];
    #pragma unroll
    for (int mt = 0; mt < 2; mt++)
        #pragma unroll
        for (int h = 0; h < 2; h++) {
            int iL = mb + mt * 16 + r + h * 8;
            sqi_r[mt * 2 + h] = s_sqi[iL]; li_r[mt * 2 + h] = s_li[iL];
        }
    float sqj_r[16]; int lj_r[16];
    #pragma unroll
    for (int nt = 0; nt < 8; nt++)
        #pragma unroll
        for (int o = 0; o < 2; o++) {
            int jL = nb + nt * 8 + cb + o;
            sqj_r[nt * 2 + o] = s_sqj[jL]; lj_r[nt * 2 + o] = s_lj[jL];
        }

    float rp[4] = {0.f, 0.f, 0.f, 0.f};
    float cp[16];
    #pragma unroll
    for (int q = 0; q < 16; q++) cp[q] = 0.0f;

    #pragma unroll
    for (int mt = 0; mt < 2; mt++)
        #pragma unroll
        for (int nt = 0; nt < 8; nt++)
            #pragma unroll
            for (int e = 0; e < 4; e++) {
                const int h = e >> 1, o = e & 1;
                float dot = acc[mt][nt][e];
                float d2 = fmaxf(sqi_r[mt*2+h] + sqj_r[nt*2+o] - 2.0f * dot, EPSV);
                float d;
                asm("sqrt.approx.f32 %0, %1;" : "=f"(d) : "f"(d2));
                if (li_r[mt*2+h] != lj_r[nt*2+o]) {
                    float ex = __expf(MARGIN - d);
                    rp[mt*2+h] += ex;
                    cp[nt*2+o] += ex;
                } else {
                    unsigned k = atomicAdd(s_cnt, 1u);
                    if (k < PBUF_CAP) {
                        unsigned gi = it * TILE + mb + mt * 16 + r + h * 8;
                        unsigned gj = jt * TILE + nb + nt * 8 + cb + o;
                        unsigned packed = gi | (gj << 13) | (offdiag ? (1u << 26) : 0u);
                        ((uint2*)(smem + SM_PBUF))[k] = make_uint2(packed, __float_as_uint(d));
                    }
                }
            }

    // row sums: reduce across lanes sharing the same r (lane&3 axis)
    #pragma unroll
    for (int q = 0; q < 4; q++) {
        float v = rp[q];
        v += __shfl_xor_sync(0xffffffffu, v, 1);
        v += __shfl_xor_sync(0xffffffffu, v, 2);
        if ((lane & 3) == 0) {
            int iL = mb + (q >> 1) * 16 + r + (q & 1) * 8;
            atomicAdd(&s_rowS[iL], v);
        }
    }
    // col sums: reduce across lanes sharing the same c (lane>>2 axis)
    if (offdiag) {
        #pragma unroll
        for (int q = 0; q < 16; q++) {
            float v = cp[q];
            v += __shfl_xor_sync(0xffffffffu, v, 4);
            v += __shfl_xor_sync(0xffffffffu, v, 8);
            v += __shfl_xor_sync(0xffffffffu, v, 16);
            if ((lane >> 2) == 0) {
                int jL = nb + (q >> 1) * 8 + cb + (q & 1);
                atomicAdd(&s_colS[jL], v);
            }
        }
    }
    __syncthreads();

    if (t < 128) atomicAdd(&g_S[it * TILE + t], s_rowS[t]);
    else if (offdiag) atomicAdd(&g_S[jt * TILE + (t - 128)], s_colS[t - 128]);

    // flush pair buffer
    unsigned cnt = *s_cnt;
    if (cnt > PBUF_CAP) cnt = PBUF_CAP;
    if (t == 0) *s_gb = atomicAdd(&g_np, cnt);
    __syncthreads();
    unsigned gb = *s_gb;
    for (unsigned k = t; k < cnt; k += 256)
        if (gb + k < PAIR_CAP) g_pairs[gb + k] = ((uint2*)(smem + SM_PBUF))[k];
}

// ---------------- positive-pair loss ----------------
__global__ void __launch_bounds__(256) k_pairs() {
    __shared__ float rf[256];
    __shared__ int   ri[256];
    unsigned n = g_np; if (n > PAIR_CAP) n = PAIR_CAP;
    float part = 0.0f; int c = 0;
    for (unsigned idx = blockIdx.x * 256u + threadIdx.x; idx < n; idx += gridDim.x * 256u) {
        uint2 p = g_pairs[idx];
        int i = p.x & 0x1FFF, j = (p.x >> 13) & 0x1FFF;
        int wt = (p.x & (1u << 26)) ? 2 : 1;
        float d = __uint_as_float(p.y);
        float J = logf(g_S[i] + g_S[j]) + d;
        float h = fmaxf(J, 0.0f);
        part += (float)wt * h * h; c += wt;
    }
    int t = threadIdx.x;
    rf[t] = part; ri[t] = c;
    __syncthreads();
    for (int off = 128; off; off >>= 1) {
        if (t < off) { rf[t] += rf[t + off]; ri[t] += ri[t + off]; }
        __syncthreads();
    }
    if (t == 0) {
        atomicAdd(&g_loss, (double)rf[0]);
        atomicAdd(&g_cnt, (unsigned long long)ri[0]);
    }
}

__global__ void k_final(float* out) {
    out[0] = (float)(g_loss / (2.0 * (double)g_cnt));
}

// ---------------- launcher ----------------
extern "C" void kernel_launch(void* const* d_in, const int* in_sizes, int n_in,
                              void* d_out, int out_size) {
    const float* f     = (const float*)d_in[0];
    const int*   lab32 = (const int*)d_in[1];
    float*       out   = (float*)d_out;

    cudaFuncSetAttribute(k_S, cudaFuncAttributeMaxDynamicSharedMemorySize, SM_TOTAL);

    k_detect<<<1, 256>>>(lab32);
    k_conv<<<NPTS / 256, 256>>>(lab32);
    k_init<<<NPTS / 256, 256>>>();
    k_sq<<<NPTS / 8, 256>>>(f);
    k_split<<<(NPTS * DIM / 8) / 256, 256>>>(f);
    k_S<<<NTILES, 256, SM_TOTAL>>>();
    k_pairs<<<512, 256>>>();
    k_final<<<1, 1>>>(out);
}

// round 7
// speedup vs baseline: 6.3881x; 1.2052x over previous
#include <cuda_runtime.h>
#include <cuda_bf16.h>

#define NPTS 8192
#define DIM  128
#define TILE 128
#define NT   (NPTS/TILE)          // 64
#define NTILES (NT*(NT+1)/2)      // 2080
#define MARGIN 1.0f
#define EPSV 1e-16f
#define PAIR_CAP 2500000

// ---------------- device scratch ----------------
__device__ float g_S[NPTS];
__device__ float g_sq[NPTS];
__device__ int   g_lab[NPTS];
__device__ double g_loss;
__device__ unsigned long long g_cnt;
__device__ unsigned g_np;
__device__ uint4 g_hi[NPTS*DIM/8];   // 2048 uint4 granules per 128-row tile
__device__ uint4 g_lo[NPTS*DIM/8];
__device__ uint2 g_pairs[PAIR_CAP];

// ---------------- smem layout (bytes) ----------------
// A_hi 32K | A_lo 32K | B[2] x (hi 32K + lo 32K) | misc | pbuf 8K
#define SM_AH   0
#define SM_AL   32768
#define SM_B(b) (65536 + (b)*65536)     // hi at +0, lo at +32768
#define SM_MISC 196608
#define SM_SQI  (SM_MISC)
#define SM_LI   (SM_MISC + 512)
#define SM_SQJ  (SM_MISC + 1024)
#define SM_LJ   (SM_MISC + 1536)
#define SM_ROWS (SM_MISC + 2048)
#define SM_COLS (SM_MISC + 2560)
#define SM_CNT  (SM_MISC + 3072)
#define SM_GB   (SM_MISC + 3076)
#define SM_PBUF (SM_MISC + 3104)
#define PBUF_CAP 1024
#define SM_TOTAL (SM_PBUF + PBUF_CAP*8)

__device__ __forceinline__ unsigned smem_u32(const void* p) {
    unsigned a;
    asm("{ .reg .u64 t; cvta.to.shared.u64 t, %1; cvt.u32.u64 %0, t; }" : "=r"(a) : "l"(p));
    return a;
}

#define LDGSTS16(dst, src) asm volatile("cp.async.cg.shared.global [%0], [%1], 16;" :: "r"(dst), "l"(src) : "memory")
#define CP_COMMIT() asm volatile("cp.async.commit_group;" ::: "memory")
#define CP_WAIT1()  asm volatile("cp.async.wait_group 1;" ::: "memory")
#define CP_WAIT0()  asm volatile("cp.async.wait_group 0;" ::: "memory")

#define LDSM4(R, a) asm volatile( \
    "ldmatrix.sync.aligned.m8n8.x4.shared.b16 {%0,%1,%2,%3}, [%4];" \
    : "=r"((R)[0]), "=r"((R)[1]), "=r"((R)[2]), "=r"((R)[3]) : "r"(a))

#define MMA(d, a, b) asm volatile( \
    "mma.sync.aligned.m16n8k16.row.col.f32.bf16.bf16.f32 " \
    "{%0,%1,%2,%3}, {%4,%5,%6,%7}, {%8,%9}, {%0,%1,%2,%3};" \
    : "+f"((d)[0]), "+f"((d)[1]), "+f"((d)[2]), "+f"((d)[3]) \
    : "r"((a)[0]), "r"((a)[1]), "r"((a)[2]), "r"((a)[3]), "r"((b)[0]), "r"((b)[1]))

// ---------------- fused prep: split + sq + labels + init ----------------
__global__ void __launch_bounds__(256) k_prep(const float* __restrict__ f,
                                              const int* __restrict__ lab32) {
    const int b = blockIdx.x, t = threadIdx.x;
    const int idx = b * 256 + t;                 // 0..131071 (uint4 granule)
    const float4* f4 = (const float4*)f;
    float4 a = f4[idx * 2], c = f4[idx * 2 + 1];
    float v[8] = {a.x, a.y, a.z, a.w, c.x, c.y, c.z, c.w};
    unsigned hw[4], lw[4];
    float s = 0.0f;
    #pragma unroll
    for (int p = 0; p < 4; p++) {
        float x0 = v[2 * p], x1 = v[2 * p + 1];
        s = fmaf(x0, x0, s); s = fmaf(x1, x1, s);
        __nv_bfloat16 bh0 = __float2bfloat16(x0);
        __nv_bfloat16 bh1 = __float2bfloat16(x1);
        __nv_bfloat16 bl0 = __float2bfloat16(x0 - __bfloat162float(bh0));
        __nv_bfloat16 bl1 = __float2bfloat16(x1 - __bfloat162float(bh1));
        hw[p] = (unsigned)__bfloat16_as_ushort(bh0) | ((unsigned)__bfloat16_as_ushort(bh1) << 16);
        lw[p] = (unsigned)__bfloat16_as_ushort(bl0) | ((unsigned)__bfloat16_as_ushort(bl1) << 16);
    }
    g_hi[idx] = make_uint4(hw[0], hw[1], hw[2], hw[3]);
    g_lo[idx] = make_uint4(lw[0], lw[1], lw[2], lw[3]);
    // row-sq: 16 consecutive lanes hold one row's 8-elem partials
    s += __shfl_xor_sync(0xffffffffu, s, 1);
    s += __shfl_xor_sync(0xffffffffu, s, 2);
    s += __shfl_xor_sync(0xffffffffu, s, 4);
    s += __shfl_xor_sync(0xffffffffu, s, 8);
    if ((t & 15) == 0) g_sq[idx >> 4] = s;
    // labels + init (blocks 0..31 cover all 8192 points)
    if (b < 32) {
        int odd = lab32[2 * t + 1];              // sample 256 odd words
        int nz = __syncthreads_or(odd != 0);     // nz -> int32 labels
        g_lab[idx] = lab32[idx * (nz ? 1 : 2)];
        g_S[idx] = 0.0f;
        if (idx == 0) { g_loss = 0.0; g_cnt = 0ull; g_np = 0u; }
    }
}

// ---------------- stage helpers ----------------
// 256B rows, 16B granules, swizzle: granule q at row r -> q ^ (r&7)
__device__ __forceinline__ void issue_B(unsigned sb, int buf, int jt, int t) {
    const char* sh = (const char*)(g_hi + (size_t)jt * 2048);
    const char* sl = (const char*)(g_lo + (size_t)jt * 2048);
    const unsigned db = sb + SM_B(buf);
    #pragma unroll
    for (int i = 0; i < 8; i++) {
        int g = i * 256 + t;
        int r = g >> 4, q = g & 15;
        unsigned dsw = (unsigned)(r * 256 + ((q ^ (r & 7)) << 4));
        LDGSTS16(db + dsw,         sh + (size_t)g * 16);
        LDGSTS16(db + 32768 + dsw, sl + (size_t)g * 16);
    }
}
__device__ __forceinline__ void load_A(char* smem, int it, int t) {
    const uint4* sh = g_hi + (size_t)it * 2048;
    const uint4* sl = g_lo + (size_t)it * 2048;
    #pragma unroll
    for (int i = 0; i < 8; i++) {
        int g = i * 256 + t;
        int r = g >> 4, q = g & 15;
        unsigned dsw = (unsigned)(r * 256 + ((q ^ (r & 7)) << 4));
        *(uint4*)(smem + SM_AH + dsw) = sh[g];
        *(uint4*)(smem + SM_AL + dsw) = sl[g];
    }
}

// ---------------- persistent HMMA Gram + fused epilogue ----------------
__global__ void __launch_bounds__(256, 1) k_S() {
    extern __shared__ char smem[];
    const unsigned sb = smem_u32(smem);
    float* s_sqi  = (float*)(smem + SM_SQI);
    int*   s_li   = (int*)  (smem + SM_LI);
    float* s_sqj  = (float*)(smem + SM_SQJ);
    int*   s_lj   = (int*)  (smem + SM_LJ);
    float* s_rowS = (float*)(smem + SM_ROWS);
    float* s_colS = (float*)(smem + SM_COLS);
    unsigned* s_cnt = (unsigned*)(smem + SM_CNT);
    unsigned* s_gb  = (unsigned*)(smem + SM_GB);
    uint2* pbuf = (uint2*)(smem + SM_PBUF);

    const int t = threadIdx.x, w = t >> 5, lane = t & 31;

    const int nchunk = (NTILES + gridDim.x - 1) / gridDim.x;
    const int start = blockIdx.x * nchunk;
    const int end = min(start + nchunk, NTILES);
    if (start >= end) return;

    // tile coords of 'start' in upper-triangle enumeration
    int cit = 0, base = 0;
    while (start >= base + (NT - cit)) { base += NT - cit; cit++; }
    int cjt = cit + (start - base);

    // prefetch pipeline (depth 2)
    int pit = cit, pjt = cjt;
    issue_B(sb, start & 1, pjt, t); CP_COMMIT();
    { pjt++; if (pjt == NT) { pit++; pjt = pit; } }
    if (start + 1 < end) {
        issue_B(sb, (start + 1) & 1, pjt, t); CP_COMMIT();
        pjt++; if (pjt == NT) { pit++; pjt = pit; }
    }

    // warp subtile: 32 rows x 64 cols
    const int mb = (w & 3) * 32;
    const int nb = (w >> 2) * 64;
    const int a_row = mb + (lane & 15);
    const int a_ch  = lane >> 4;
    const int b_row = nb + (lane & 7) + ((lane >> 4) << 3);
    const int b_ch  = (lane >> 3) & 1;

    int curA = -1;

    for (int k = start; k < end; k++) {
        const int buf = k & 1;
        const bool offdiag = (cit != cjt);
        if (k + 1 < end) CP_WAIT1(); else CP_WAIT0();

        if (cit != curA) {
            __syncthreads();
            if (curA >= 0 && t < 128) atomicAdd(&g_S[curA * TILE + t], s_rowS[t]);
            load_A(smem, cit, t);
            if (t < 128) {
                s_sqi[t] = g_sq[cit * TILE + t];
                s_li[t]  = g_lab[cit * TILE + t];
                s_rowS[t] = 0.0f;
            }
            curA = cit;
        }
        if (t < 128) {
            s_sqj[t] = g_sq[cjt * TILE + t];
            s_lj[t]  = g_lab[cjt * TILE + t];
            s_colS[t] = 0.0f;
        }
        if (t == 0) *s_cnt = 0u;
        __syncthreads();

        // ---- MMA: 3 products hi*hi + hi*lo + lo*hi ----
        float acc[2][8][4];
        #pragma unroll
        for (int mt = 0; mt < 2; mt++)
            #pragma unroll
            for (int nt = 0; nt < 8; nt++)
                #pragma unroll
                for (int e = 0; e < 4; e++) acc[mt][nt][e] = 0.0f;

        const unsigned bbase = sb + SM_B(buf);
        #pragma unroll
        for (int ks = 0; ks < 8; ks++) {
            unsigned ah[2][4], al[2][4], bh[8][2], bl[8][2];
            #pragma unroll
            for (int mt = 0; mt < 2; mt++) {
                int r = a_row + mt * 16;
                unsigned addr = sb + SM_AH + r * 256 + (((ks * 2 + a_ch) ^ (r & 7)) << 4);
                LDSM4(ah[mt], addr);
                LDSM4(al[mt], addr + 32768);
            }
            #pragma unroll
            for (int np = 0; np < 4; np++) {
                int r = b_row + np * 16;
                unsigned addr = bbase + r * 256 + (((ks * 2 + b_ch) ^ (r & 7)) << 4);
                unsigned th[4], tl[4];
                LDSM4(th, addr);
                LDSM4(tl, addr + 32768);
                bh[2*np][0] = th[0]; bh[2*np][1] = th[1]; bh[2*np+1][0] = th[2]; bh[2*np+1][1] = th[3];
                bl[2*np][0] = tl[0]; bl[2*np][1] = tl[1]; bl[2*np+1][0] = tl[2]; bl[2*np+1][1] = tl[3];
            }
            #pragma unroll
            for (int mt = 0; mt < 2; mt++)
                #pragma unroll
                for (int nt = 0; nt < 8; nt++) {
                    MMA(acc[mt][nt], ah[mt], bh[nt]);
                    MMA(acc[mt][nt], ah[mt], bl[nt]);
                    MMA(acc[mt][nt], al[mt], bh[nt]);
                }
        }
        __syncthreads();   // all warps done reading B(buf)

        // prefetch B(k+2) into this buffer; overlaps epilogue
        if (k + 2 < end) {
            issue_B(sb, buf, pjt, t); CP_COMMIT();
            pjt++; if (pjt == NT) { pit++; pjt = pit; }
        }

        // ---- epilogue ----
        const int r4 = lane >> 2, cb = (lane & 3) * 2;
        float sqi_r[4]; int li_r[4];
        #pragma unroll
        for (int mt = 0; mt < 2; mt++)
            #pragma unroll
            for (int h = 0; h < 2; h++) {
                int iL = mb + mt * 16 + r4 + h * 8;
                sqi_r[mt*2+h] = s_sqi[iL]; li_r[mt*2+h] = s_li[iL];
            }
        float sqj_r[16]; int lj_r[16];
        #pragma unroll
        for (int nt = 0; nt < 8; nt++)
            #pragma unroll
            for (int o = 0; o < 2; o++) {
                int jL = nb + nt * 8 + cb + o;
                sqj_r[nt*2+o] = s_sqj[jL]; lj_r[nt*2+o] = s_lj[jL];
            }

        float rp[4] = {0.f, 0.f, 0.f, 0.f};
        float cp[16];
        #pragma unroll
        for (int q = 0; q < 16; q++) cp[q] = 0.0f;

        #pragma unroll
        for (int mt = 0; mt < 2; mt++)
            #pragma unroll
            for (int nt = 0; nt < 8; nt++)
                #pragma unroll
                for (int e = 0; e < 4; e++) {
                    const int h = e >> 1, o = e & 1;
                    float d2 = fmaxf(sqi_r[mt*2+h] + sqj_r[nt*2+o] - 2.0f * acc[mt][nt][e], EPSV);
                    float d;
                    asm("sqrt.approx.f32 %0, %1;" : "=f"(d) : "f"(d2));
                    if (li_r[mt*2+h] != lj_r[nt*2+o]) {
                        float ex = __expf(MARGIN - d);
                        rp[mt*2+h] += ex;
                        cp[nt*2+o] += ex;
                    } else {
                        unsigned kk = atomicAdd(s_cnt, 1u);
                        unsigned gi = cit * TILE + mb + mt * 16 + r4 + h * 8;
                        unsigned gj = cjt * TILE + nb + nt * 8 + cb + o;
                        unsigned packed = gi | (gj << 13) | (offdiag ? (1u << 26) : 0u);
                        uint2 rec = make_uint2(packed, __float_as_uint(d));
                        if (kk < PBUF_CAP) pbuf[kk] = rec;
                        else { unsigned gg = atomicAdd(&g_np, 1u); if (gg < PAIR_CAP) g_pairs[gg] = rec; }
                    }
                }

        #pragma unroll
        for (int q = 0; q < 4; q++) {
            float v = rp[q];
            v += __shfl_xor_sync(0xffffffffu, v, 1);
            v += __shfl_xor_sync(0xffffffffu, v, 2);
            if ((lane & 3) == 0)
                atomicAdd(&s_rowS[mb + (q >> 1) * 16 + r4 + (q & 1) * 8], v);
        }
        if (offdiag) {
            #pragma unroll
            for (int q = 0; q < 16; q++) {
                float v = cp[q];
                v += __shfl_xor_sync(0xffffffffu, v, 4);
                v += __shfl_xor_sync(0xffffffffu, v, 8);
                v += __shfl_xor_sync(0xffffffffu, v, 16);
                if ((lane >> 2) == 0)
                    atomicAdd(&s_colS[nb + (q >> 1) * 8 + cb + (q & 1)], v);
            }
        }
        __syncthreads();

        if (offdiag && t < 128) atomicAdd(&g_S[cjt * TILE + t], s_colS[t]);

        // flush pair buffer
        unsigned cnt = *s_cnt;
        if (cnt > PBUF_CAP) cnt = PBUF_CAP;
        if (t == 0) *s_gb = atomicAdd(&g_np, cnt);
        __syncthreads();
        unsigned gbv = *s_gb;
        for (unsigned k2 = t; k2 < cnt; k2 += 256)
            if (gbv + k2 < PAIR_CAP) g_pairs[gbv + k2] = pbuf[k2];
        __syncthreads();

        cjt++; if (cjt == NT) { cit++; cjt = cit; }
    }

    if (curA >= 0 && t < 128) atomicAdd(&g_S[curA * TILE + t], s_rowS[t]);
}

// ---------------- positive-pair loss ----------------
__global__ void __launch_bounds__(256) k_pairs() {
    __shared__ float rf[256];
    __shared__ int   ri[256];
    unsigned n = g_np; if (n > PAIR_CAP) n = PAIR_CAP;
    float part = 0.0f; int c = 0;
    for (unsigned idx = blockIdx.x * 256u + threadIdx.x; idx < n; idx += gridDim.x * 256u) {
        uint2 p = g_pairs[idx];
        int i = p.x & 0x1FFF, j = (p.x >> 13) & 0x1FFF;
        int wt = (p.x & (1u << 26)) ? 2 : 1;
        float d = __uint_as_float(p.y);
        float J = logf(g_S[i] + g_S[j]) + d;
        float h = fmaxf(J, 0.0f);
        part += (float)wt * h * h; c += wt;
    }
    int t = threadIdx.x;
    rf[t] = part; ri[t] = c;
    __syncthreads();
    for (int off = 128; off; off >>= 1) {
        if (t < off) { rf[t] += rf[t + off]; ri[t] += ri[t + off]; }
        __syncthreads();
    }
    if (t == 0) {
        atomicAdd(&g_loss, (double)rf[0]);
        atomicAdd(&g_cnt, (unsigned long long)ri[0]);
    }
}

__global__ void k_final(float* out) {
    out[0] = (float)(g_loss / (2.0 * (double)g_cnt));
}

// ---------------- launcher ----------------
extern "C" void kernel_launch(void* const* d_in, const int* in_sizes, int n_in,
                              void* d_out, int out_size) {
    const float* f     = (const float*)d_in[0];
    const int*   lab32 = (const int*)d_in[1];
    float*       out   = (float*)d_out;

    int dev = 0, nsm = 0;
    if (cudaGetDevice(&dev) != cudaSuccess ||
        cudaDeviceGetAttribute(&nsm, cudaDevAttrMultiProcessorCount, dev) != cudaSuccess ||
        nsm <= 0)
        nsm = 148;

    cudaFuncSetAttribute(k_S, cudaFuncAttributeMaxDynamicSharedMemorySize, SM_TOTAL);

    k_prep<<<512, 256>>>(f, lab32);
    k_S<<<nsm, 256, SM_TOTAL>>>();
    k_pairs<<<512, 256>>>();
    k_final<<<1, 1>>>(out);
}

// round 8
// speedup vs baseline: 12.2497x; 1.9176x over previous
#include <cuda_runtime.h>
#include <cuda_fp16.h>

#define NPTS 8192
#define DIM  128
#define TILE 128
#define NT   (NPTS/TILE)          // 64
#define NTILES (NT*(NT+1)/2)      // 2080
#define MARGIN 1.0f
#define EPSV 1e-16f
#define PAIR_CAP 2500000

// ---------------- device scratch ----------------
__device__ float g_S[NPTS];
__device__ float g_sq[NPTS];
__device__ int   g_lab[NPTS];
__device__ double g_loss;
__device__ unsigned long long g_cnt;
__device__ unsigned g_np;
__device__ unsigned g_done;
__device__ uint4 g_h[NPTS*DIM/8];    // fp16 features, 8 per uint4
__device__ uint2 g_pairs[PAIR_CAP];

// ---------------- smem layout (bytes) ----------------
// A 32K | B[2] 2x32K | misc | pbuf 8K  => 109600 B (2 CTAs/SM)
#define SM_AH   0
#define SM_B(b) (32768 + (b)*32768)
#define SM_MISC 98304
#define SM_SQI  (SM_MISC)
#define SM_LI   (SM_MISC + 512)
#define SM_SQJ  (SM_MISC + 1024)
#define SM_LJ   (SM_MISC + 1536)
#define SM_ROWS (SM_MISC + 2048)
#define SM_COLS (SM_MISC + 2560)
#define SM_CNT  (SM_MISC + 3072)
#define SM_GB   (SM_MISC + 3076)
#define SM_PBUF (SM_MISC + 3104)
#define PBUF_CAP 1024
#define SM_TOTAL (SM_PBUF + PBUF_CAP*8)

__device__ __forceinline__ unsigned smem_u32(const void* p) {
    unsigned a;
    asm("{ .reg .u64 t; cvta.to.shared.u64 t, %1; cvt.u32.u64 %0, t; }" : "=r"(a) : "l"(p));
    return a;
}

#define LDGSTS16(dst, src) asm volatile("cp.async.cg.shared.global [%0], [%1], 16;" :: "r"(dst), "l"(src) : "memory")
#define CP_COMMIT() asm volatile("cp.async.commit_group;" ::: "memory")
#define CP_WAIT1()  asm volatile("cp.async.wait_group 1;" ::: "memory")
#define CP_WAIT0()  asm volatile("cp.async.wait_group 0;" ::: "memory")

#define LDSM4(R, a) asm volatile( \
    "ldmatrix.sync.aligned.m8n8.x4.shared.b16 {%0,%1,%2,%3}, [%4];" \
    : "=r"((R)[0]), "=r"((R)[1]), "=r"((R)[2]), "=r"((R)[3]) : "r"(a))

#define MMA(d, a, b) asm volatile( \
    "mma.sync.aligned.m16n8k16.row.col.f32.f16.f16.f32 " \
    "{%0,%1,%2,%3}, {%4,%5,%6,%7}, {%8,%9}, {%0,%1,%2,%3};" \
    : "+f"((d)[0]), "+f"((d)[1]), "+f"((d)[2]), "+f"((d)[3]) \
    : "r"((a)[0]), "r"((a)[1]), "r"((a)[2]), "r"((a)[3]), "r"((b)[0]), "r"((b)[1]))

// ---------------- fused prep: fp16 convert + sq + labels + init ----------------
__global__ void __launch_bounds__(256) k_prep(const float* __restrict__ f,
                                              const int* __restrict__ lab32) {
    const int b = blockIdx.x, t = threadIdx.x;
    const int idx = b * 256 + t;                 // 0..131071 (8-float granule)
    const float4* f4 = (const float4*)f;
    float4 a = f4[idx * 2], c = f4[idx * 2 + 1];
    __half2 h0 = __floats2half2_rn(a.x, a.y);
    __half2 h1 = __floats2half2_rn(a.z, a.w);
    __half2 h2 = __floats2half2_rn(c.x, c.y);
    __half2 h3 = __floats2half2_rn(c.z, c.w);
    g_h[idx] = make_uint4(*(unsigned*)&h0, *(unsigned*)&h1, *(unsigned*)&h2, *(unsigned*)&h3);
    float s = 0.0f;
    s = fmaf(a.x, a.x, s); s = fmaf(a.y, a.y, s);
    s = fmaf(a.z, a.z, s); s = fmaf(a.w, a.w, s);
    s = fmaf(c.x, c.x, s); s = fmaf(c.y, c.y, s);
    s = fmaf(c.z, c.z, s); s = fmaf(c.w, c.w, s);
    // row-sq: 16 consecutive lanes hold one row's partials
    s += __shfl_xor_sync(0xffffffffu, s, 1);
    s += __shfl_xor_sync(0xffffffffu, s, 2);
    s += __shfl_xor_sync(0xffffffffu, s, 4);
    s += __shfl_xor_sync(0xffffffffu, s, 8);
    if ((t & 15) == 0) g_sq[idx >> 4] = s;
    // labels + init (blocks 0..31 cover all 8192 points)
    if (b < 32) {
        int odd = lab32[2 * t + 1];
        int nz = __syncthreads_or(odd != 0);     // nz -> int32 labels
        g_lab[idx] = lab32[idx * (nz ? 1 : 2)];
        g_S[idx] = 0.0f;
        if (idx == 0) { g_loss = 0.0; g_cnt = 0ull; g_np = 0u; g_done = 0u; }
    }
}

// ---------------- stage helpers ----------------
// 256B rows, 16B granules, swizzle: granule q at row r -> q ^ (r&7)
__device__ __forceinline__ void issue_B(unsigned sb, int buf, int jt, int t) {
    const char* sh = (const char*)(g_h + (size_t)jt * 2048);
    const unsigned db = sb + SM_B(buf);
    #pragma unroll
    for (int i = 0; i < 8; i++) {
        int g = i * 256 + t;
        int r = g >> 4, q = g & 15;
        unsigned dsw = (unsigned)(r * 256 + ((q ^ (r & 7)) << 4));
        LDGSTS16(db + dsw, sh + (size_t)g * 16);
    }
}
__device__ __forceinline__ void load_A(char* smem, int it, int t) {
    const uint4* sh = g_h + (size_t)it * 2048;
    #pragma unroll
    for (int i = 0; i < 8; i++) {
        int g = i * 256 + t;
        int r = g >> 4, q = g & 15;
        unsigned dsw = (unsigned)(r * 256 + ((q ^ (r & 7)) << 4));
        *(uint4*)(smem + SM_AH + dsw) = sh[g];
    }
}

// ---------------- persistent HMMA Gram + fused epilogue ----------------
__global__ void __launch_bounds__(256, 2) k_S() {
    extern __shared__ char smem[];
    const unsigned sb = smem_u32(smem);
    float* s_sqi  = (float*)(smem + SM_SQI);
    int*   s_li   = (int*)  (smem + SM_LI);
    float* s_sqj  = (float*)(smem + SM_SQJ);
    int*   s_lj   = (int*)  (smem + SM_LJ);
    float* s_rowS = (float*)(smem + SM_ROWS);
    float* s_colS = (float*)(smem + SM_COLS);
    unsigned* s_cnt = (unsigned*)(smem + SM_CNT);
    unsigned* s_gb  = (unsigned*)(smem + SM_GB);
    uint2* pbuf = (uint2*)(smem + SM_PBUF);

    const int t = threadIdx.x, w = t >> 5, lane = t & 31;

    // balanced contiguous split
    const int nb_ = gridDim.x;
    const int basec = NTILES / nb_, rem = NTILES % nb_;
    const int start = blockIdx.x * basec + min(blockIdx.x, rem);
    const int end = start + basec + (blockIdx.x < rem ? 1 : 0);
    if (start >= end) return;

    int cit = 0, base = 0;
    while (start >= base + (NT - cit)) { base += NT - cit; cit++; }
    int cjt = cit + (start - base);

    // prefetch pipeline (depth 2)
    int pit = cit, pjt = cjt;
    issue_B(sb, start & 1, pjt, t); CP_COMMIT();
    { pjt++; if (pjt == NT) { pit++; pjt = pit; } }
    if (start + 1 < end) {
        issue_B(sb, (start + 1) & 1, pjt, t); CP_COMMIT();
        pjt++; if (pjt == NT) { pit++; pjt = pit; }
    }

    // warp subtile: 32 rows x 64 cols
    const int mb = (w & 3) * 32;
    const int nb = (w >> 2) * 64;
    const int a_row = mb + (lane & 15);
    const int a_ch  = lane >> 4;
    const int b_row = nb + (lane & 7) + ((lane >> 4) << 3);
    const int b_ch  = (lane >> 3) & 1;

    int curA = -1;

    for (int k = start; k < end; k++) {
        const int buf = k & 1;
        const bool offdiag = (cit != cjt);
        if (k + 1 < end) CP_WAIT1(); else CP_WAIT0();

        if (cit != curA) {
            __syncthreads();
            if (curA >= 0 && t < 128) atomicAdd(&g_S[curA * TILE + t], s_rowS[t]);
            load_A(smem, cit, t);
            if (t < 128) {
                s_sqi[t] = g_sq[cit * TILE + t];
                s_li[t]  = g_lab[cit * TILE + t];
                s_rowS[t] = 0.0f;
            }
            curA = cit;
        }
        if (t < 128) {
            s_sqj[t] = g_sq[cjt * TILE + t];
            s_lj[t]  = g_lab[cjt * TILE + t];
            s_colS[t] = 0.0f;
        }
        if (t == 0) *s_cnt = 0u;
        __syncthreads();

        // ---- MMA: single fp16 product ----
        float acc[2][8][4];
        #pragma unroll
        for (int mt = 0; mt < 2; mt++)
            #pragma unroll
            for (int nt = 0; nt < 8; nt++)
                #pragma unroll
                for (int e = 0; e < 4; e++) acc[mt][nt][e] = 0.0f;

        const unsigned bbase = sb + SM_B(buf);
        #pragma unroll
        for (int ks = 0; ks < 8; ks++) {
            unsigned ah[2][4], bh[8][2];
            #pragma unroll
            for (int mt = 0; mt < 2; mt++) {
                int r = a_row + mt * 16;
                unsigned addr = sb + SM_AH + r * 256 + (((ks * 2 + a_ch) ^ (r & 7)) << 4);
                LDSM4(ah[mt], addr);
            }
            #pragma unroll
            for (int np = 0; np < 4; np++) {
                int r = b_row + np * 16;
                unsigned addr = bbase + r * 256 + (((ks * 2 + b_ch) ^ (r & 7)) << 4);
                unsigned th[4];
                LDSM4(th, addr);
                bh[2*np][0] = th[0]; bh[2*np][1] = th[1];
                bh[2*np+1][0] = th[2]; bh[2*np+1][1] = th[3];
            }
            #pragma unroll
            for (int mt = 0; mt < 2; mt++)
                #pragma unroll
                for (int nt = 0; nt < 8; nt++)
                    MMA(acc[mt][nt], ah[mt], bh[nt]);
        }
        __syncthreads();   // all warps done reading B(buf)

        // prefetch B(k+2) into this buffer; overlaps epilogue
        if (k + 2 < end) {
            issue_B(sb, buf, pjt, t); CP_COMMIT();
            pjt++; if (pjt == NT) { pit++; pjt = pit; }
        }

        // ---- epilogue ----
        const int r4 = lane >> 2, cb = (lane & 3) * 2;
        float sqi_r[4]; int li_r[4];
        #pragma unroll
        for (int mt = 0; mt < 2; mt++)
            #pragma unroll
            for (int h = 0; h < 2; h++) {
                int iL = mb + mt * 16 + r4 + h * 8;
                sqi_r[mt*2+h] = s_sqi[iL]; li_r[mt*2+h] = s_li[iL];
            }

        float rp[4] = {0.f, 0.f, 0.f, 0.f};
        float cp[16];
        #pragma unroll
        for (int q = 0; q < 16; q++) cp[q] = 0.0f;

        #pragma unroll
        for (int mt = 0; mt < 2; mt++)
            #pragma unroll
            for (int nt = 0; nt < 8; nt++)
                #pragma unroll
                for (int e = 0; e < 4; e++) {
                    const int h = e >> 1, o = e & 1;
                    const int jL = nb + nt * 8 + cb + o;
                    float d2 = fmaxf(sqi_r[mt*2+h] + s_sqj[jL] - 2.0f * acc[mt][nt][e], EPSV);
                    float d;
                    asm("sqrt.approx.f32 %0, %1;" : "=f"(d) : "f"(d2));
                    if (li_r[mt*2+h] != s_lj[jL]) {
                        float ex = __expf(MARGIN - d);
                        rp[mt*2+h] += ex;
                        cp[nt*2+o] += ex;
                    } else {
                        unsigned kk = atomicAdd(s_cnt, 1u);
                        unsigned gi = cit * TILE + mb + mt * 16 + r4 + h * 8;
                        unsigned gj = cjt * TILE + jL;
                        unsigned packed = gi | (gj << 13) | (offdiag ? (1u << 26) : 0u);
                        uint2 rec = make_uint2(packed, __float_as_uint(d));
                        if (kk < PBUF_CAP) pbuf[kk] = rec;
                        else { unsigned gg = atomicAdd(&g_np, 1u); if (gg < PAIR_CAP) g_pairs[gg] = rec; }
                    }
                }

        #pragma unroll
        for (int q = 0; q < 4; q++) {
            float v = rp[q];
            v += __shfl_xor_sync(0xffffffffu, v, 1);
            v += __shfl_xor_sync(0xffffffffu, v, 2);
            if ((lane & 3) == 0)
                atomicAdd(&s_rowS[mb + (q >> 1) * 16 + r4 + (q & 1) * 8], v);
        }
        if (offdiag) {
            #pragma unroll
            for (int q = 0; q < 16; q++) {
                float v = cp[q];
                v += __shfl_xor_sync(0xffffffffu, v, 4);
                v += __shfl_xor_sync(0xffffffffu, v, 8);
                v += __shfl_xor_sync(0xffffffffu, v, 16);
                if ((lane >> 2) == 0)
                    atomicAdd(&s_colS[nb + (q >> 1) * 8 + cb + (q & 1)], v);
            }
        }
        __syncthreads();

        if (offdiag && t < 128) atomicAdd(&g_S[cjt * TILE + t], s_colS[t]);

        // flush pair buffer
        unsigned cnt = *s_cnt;
        if (cnt > PBUF_CAP) cnt = PBUF_CAP;
        if (t == 0) *s_gb = atomicAdd(&g_np, cnt);
        __syncthreads();
        unsigned gbv = *s_gb;
        for (unsigned k2 = t; k2 < cnt; k2 += 256)
            if (gbv + k2 < PAIR_CAP) g_pairs[gbv + k2] = pbuf[k2];
        __syncthreads();

        cjt++; if (cjt == NT) { cit++; cjt = cit; }
    }

    if (curA >= 0 && t < 128) atomicAdd(&g_S[curA * TILE + t], s_rowS[t]);
}

// ---------------- positive-pair loss + fused finalize ----------------
__global__ void __launch_bounds__(256) k_pairs(float* out) {
    __shared__ float rf[256];
    __shared__ int   ri[256];
    unsigned n = g_np; if (n > PAIR_CAP) n = PAIR_CAP;
    float part = 0.0f; int c = 0;
    for (unsigned idx = blockIdx.x * 256u + threadIdx.x; idx < n; idx += gridDim.x * 256u) {
        uint2 p = g_pairs[idx];
        int i = p.x & 0x1FFF, j = (p.x >> 13) & 0x1FFF;
        int wt = (p.x & (1u << 26)) ? 2 : 1;
        float d = __uint_as_float(p.y);
        float J = logf(g_S[i] + g_S[j]) + d;
        float h = fmaxf(J, 0.0f);
        part += (float)wt * h * h; c += wt;
    }
    int t = threadIdx.x;
    rf[t] = part; ri[t] = c;
    __syncthreads();
    for (int off = 128; off; off >>= 1) {
        if (t < off) { rf[t] += rf[t + off]; ri[t] += ri[t + off]; }
        __syncthreads();
    }
    if (t == 0) {
        atomicAdd(&g_loss, (double)rf[0]);
        atomicAdd(&g_cnt, (unsigned long long)ri[0]);
        __threadfence();
        unsigned v = atomicAdd(&g_done, 1u);
        if (v == gridDim.x - 1)
            out[0] = (float)(g_loss / (2.0 * (double)g_cnt));
    }
}

// ---------------- launcher ----------------
extern "C" void kernel_launch(void* const* d_in, const int* in_sizes, int n_in,
                              void* d_out, int out_size) {
    const float* f     = (const float*)d_in[0];
    const int*   lab32 = (const int*)d_in[1];
    float*       out   = (float*)d_out;

    int dev = 0, nsm = 0;
    if (cudaGetDevice(&dev) != cudaSuccess ||
        cudaDeviceGetAttribute(&nsm, cudaDevAttrMultiProcessorCount, dev) != cudaSuccess ||
        nsm <= 0)
        nsm = 148;

    cudaFuncSetAttribute(k_S, cudaFuncAttributeMaxDynamicSharedMemorySize, SM_TOTAL);

    k_prep<<<512, 256>>>(f, lab32);
    k_S<<<nsm * 2, 256, SM_TOTAL>>>();
    k_pairs<<<512, 256>>>(out);
}